// round 1
// baseline (speedup 1.0000x reference)
#include <cuda_runtime.h>
#include <cuda_bf16.h>
#include <math.h>

// Problem shape (fixed by reference):
//   x: [M, K]  h: [M, N]  W: [N, K]  b: [N]  decay: [N]
//   out = sigmoid(decay) * h + x @ W^T + b   (written once or twice per out_size)
#define M_DIM 16384
#define N_DIM 2048
#define K_DIM 2048

// Tiling: 128x128 CTA tile, K-tile 16, 256 threads, 8x8 per-thread micro-tile.
#define BM 128
#define BN 128
#define BK 16
#define NTHREADS 256

__global__ __launch_bounds__(NTHREADS, 2)
void lrnn_sgemm_fused(const float* __restrict__ x,
                      const float* __restrict__ h,
                      const float* __restrict__ W,
                      const float* __restrict__ bias,
                      const float* __restrict__ decay,
                      float* __restrict__ out,
                      int write_twice)
{
    __shared__ float As[2][BK][BM];   // A staged transposed: As[k][m]
    __shared__ float Bs[2][BK][BN];   // B staged transposed: Bs[k][n]

    const int tid = threadIdx.x;
    const int tm = tid >> 4;          // 0..15 -> row group (8 rows each)
    const int tn = tid & 15;          // 0..15 -> col group (8 cols each)

    const int rowBase = blockIdx.y * BM;
    const int colBase = blockIdx.x * BN;

    // Global-load mapping: 128 rows x 16 cols per tile = 512 float4.
    // Each thread loads 2 float4 from A and 2 from B per K-tile.
    const int lr  = tid >> 2;         // 0..63 (row within tile, +64 for 2nd half)
    const int lc4 = (tid & 3) << 2;   // 0,4,8,12 (k-col within tile)

    const float* gA = x + (size_t)(rowBase + lr) * K_DIM + lc4;
    const float* gB = W + (size_t)(colBase + lr) * K_DIM + lc4;

    float acc[8][8];
#pragma unroll
    for (int i = 0; i < 8; ++i)
#pragma unroll
        for (int j = 0; j < 8; ++j)
            acc[i][j] = 0.0f;

    // ---- Prologue: load K-tile 0 into buffer 0 ----
    {
        float4 a0 = *(const float4*)(gA);
        float4 a1 = *(const float4*)(gA + (size_t)64 * K_DIM);
        float4 b0 = *(const float4*)(gB);
        float4 b1 = *(const float4*)(gB + (size_t)64 * K_DIM);
        As[0][lc4 + 0][lr]      = a0.x;
        As[0][lc4 + 1][lr]      = a0.y;
        As[0][lc4 + 2][lr]      = a0.z;
        As[0][lc4 + 3][lr]      = a0.w;
        As[0][lc4 + 0][lr + 64] = a1.x;
        As[0][lc4 + 1][lr + 64] = a1.y;
        As[0][lc4 + 2][lr + 64] = a1.z;
        As[0][lc4 + 3][lr + 64] = a1.w;
        Bs[0][lc4 + 0][lr]      = b0.x;
        Bs[0][lc4 + 1][lr]      = b0.y;
        Bs[0][lc4 + 2][lr]      = b0.z;
        Bs[0][lc4 + 3][lr]      = b0.w;
        Bs[0][lc4 + 0][lr + 64] = b1.x;
        Bs[0][lc4 + 1][lr + 64] = b1.y;
        Bs[0][lc4 + 2][lr + 64] = b1.z;
        Bs[0][lc4 + 3][lr + 64] = b1.w;
    }
    __syncthreads();

    const int numTiles = K_DIM / BK;   // 128
    int buf = 0;

    for (int t = 0; t < numTiles; ++t) {
        // Kick off next tile's global loads (latency overlapped with compute).
        float4 na0, na1, nb0, nb1;
        const bool has_next = (t + 1 < numTiles);
        if (has_next) {
            const size_t koff = (size_t)(t + 1) * BK;
            na0 = *(const float4*)(gA + koff);
            na1 = *(const float4*)(gA + koff + (size_t)64 * K_DIM);
            nb0 = *(const float4*)(gB + koff);
            nb1 = *(const float4*)(gB + koff + (size_t)64 * K_DIM);
        }

        // Compute on current buffer.
#pragma unroll
        for (int kk = 0; kk < BK; ++kk) {
            float a[8], b[8];
            *(float4*)(a)     = *(const float4*)&As[buf][kk][tm * 8];
            *(float4*)(a + 4) = *(const float4*)&As[buf][kk][tm * 8 + 4];
            *(float4*)(b)     = *(const float4*)&Bs[buf][kk][tn * 8];
            *(float4*)(b + 4) = *(const float4*)&Bs[buf][kk][tn * 8 + 4];
#pragma unroll
            for (int i = 0; i < 8; ++i)
#pragma unroll
                for (int j = 0; j < 8; ++j)
                    acc[i][j] = fmaf(a[i], b[j], acc[i][j]);
        }

        if (has_next) {
            const int nb = buf ^ 1;
            As[nb][lc4 + 0][lr]      = na0.x;
            As[nb][lc4 + 1][lr]      = na0.y;
            As[nb][lc4 + 2][lr]      = na0.z;
            As[nb][lc4 + 3][lr]      = na0.w;
            As[nb][lc4 + 0][lr + 64] = na1.x;
            As[nb][lc4 + 1][lr + 64] = na1.y;
            As[nb][lc4 + 2][lr + 64] = na1.z;
            As[nb][lc4 + 3][lr + 64] = na1.w;
            Bs[nb][lc4 + 0][lr]      = nb0.x;
            Bs[nb][lc4 + 1][lr]      = nb0.y;
            Bs[nb][lc4 + 2][lr]      = nb0.z;
            Bs[nb][lc4 + 3][lr]      = nb0.w;
            Bs[nb][lc4 + 0][lr + 64] = nb1.x;
            Bs[nb][lc4 + 1][lr + 64] = nb1.y;
            Bs[nb][lc4 + 2][lr + 64] = nb1.z;
            Bs[nb][lc4 + 3][lr + 64] = nb1.w;
            __syncthreads();
            buf = nb;
        }
    }

    // ---- Fused epilogue: out = acc + sigmoid(decay[n]) * h + b[n], dual write ----
    const int col0 = colBase + tn * 8;
    float alpha[8], bb[8];
#pragma unroll
    for (int j = 0; j < 8; ++j) {
        const float d = decay[col0 + j];
        alpha[j] = 1.0f / (1.0f + expf(-d));
        bb[j]    = bias[col0 + j];
    }

    const size_t dual_off = (size_t)M_DIM * N_DIM;

#pragma unroll
    for (int i = 0; i < 8; ++i) {
        const size_t roff = (size_t)(rowBase + tm * 8 + i) * N_DIM + col0;
        float4 h0 = *(const float4*)(h + roff);
        float4 h1 = *(const float4*)(h + roff + 4);

        float4 r0, r1;
        r0.x = fmaf(alpha[0], h0.x, acc[i][0] + bb[0]);
        r0.y = fmaf(alpha[1], h0.y, acc[i][1] + bb[1]);
        r0.z = fmaf(alpha[2], h0.z, acc[i][2] + bb[2]);
        r0.w = fmaf(alpha[3], h0.w, acc[i][3] + bb[3]);
        r1.x = fmaf(alpha[4], h1.x, acc[i][4] + bb[4]);
        r1.y = fmaf(alpha[5], h1.y, acc[i][5] + bb[5]);
        r1.z = fmaf(alpha[6], h1.z, acc[i][6] + bb[6]);
        r1.w = fmaf(alpha[7], h1.w, acc[i][7] + bb[7]);

        *(float4*)(out + roff)     = r0;
        *(float4*)(out + roff + 4) = r1;
        if (write_twice) {
            *(float4*)(out + dual_off + roff)     = r0;
            *(float4*)(out + dual_off + roff + 4) = r1;
        }
    }
}

extern "C" void kernel_launch(void* const* d_in, const int* in_sizes, int n_in,
                              void* d_out, int out_size)
{
    const float* x     = (const float*)d_in[0];
    const float* h     = (const float*)d_in[1];
    const float* W     = (const float*)d_in[2];
    const float* b     = (const float*)d_in[3];
    const float* decay = (const float*)d_in[4];
    float* out = (float*)d_out;

    const long long total = (long long)M_DIM * N_DIM;
    const int write_twice = ((long long)out_size >= 2 * total) ? 1 : 0;

    dim3 grid(N_DIM / BN, M_DIM / BM);   // (16, 128) = 2048 CTAs
    lrnn_sgemm_fused<<<grid, NTHREADS>>>(x, h, W, b, decay, out, write_twice);
}

// round 3
// speedup vs baseline: 1.7834x; 1.7834x over previous
#include <cuda_runtime.h>
#include <cuda_bf16.h>
#include <math.h>
#include <stdint.h>

// out = sigmoid(decay)*h + x @ W^T + b ; x:[M,K] W:[N,K] fp32
#define M_DIM 16384
#define N_DIM 2048
#define K_DIM 2048

#define BM 128
#define BN 128
#define BK 32
#define STAGES 3
#define NTHREADS 256
#define KTILES (K_DIM / BK)        // 64

#define STAGE_BYTES 32768          // A 16KB + B 16KB
#define SMEM_TOTAL (STAGES * STAGE_BYTES)

// ---- scratch: row-major bf16 hi/lo copies ----
__device__ __align__(1024) unsigned char g_xhi[(size_t)M_DIM * K_DIM * 2];
__device__ __align__(1024) unsigned char g_xlo[(size_t)M_DIM * K_DIM * 2];
__device__ __align__(1024) unsigned char g_whi[(size_t)N_DIM * K_DIM * 2];
__device__ __align__(1024) unsigned char g_wlo[(size_t)N_DIM * K_DIM * 2];
__device__ float g_alpha[N_DIM];

__device__ __forceinline__ uint32_t smem_u32(const void* p) {
    uint32_t a;
    asm("{ .reg .u64 t; cvta.to.shared.u64 t, %1; cvt.u32.u64 %0, t; }" : "=r"(a) : "l"(p));
    return a;
}

#define CP16(dst, src) \
    asm volatile("cp.async.cg.shared.global [%0], [%1], 16;" :: "r"(dst), "l"(src) : "memory")
#define CP_COMMIT() asm volatile("cp.async.commit_group;" ::: "memory")
#define CP_WAIT1()  asm volatile("cp.async.wait_group 1;" ::: "memory")

#define LDSM_X4(r0, r1, r2, r3, addr) \
    asm volatile("ldmatrix.sync.aligned.m8n8.x4.shared.b16 {%0,%1,%2,%3}, [%4];" \
        : "=r"(r0), "=r"(r1), "=r"(r2), "=r"(r3) : "r"(addr))

#define MMA_BF16(d, a, b0, b1) \
    asm volatile("mma.sync.aligned.m16n8k16.row.col.f32.bf16.bf16.f32 " \
        "{%0,%1,%2,%3}, {%4,%5,%6,%7}, {%8,%9}, {%0,%1,%2,%3};" \
        : "+f"((d)[0]), "+f"((d)[1]), "+f"((d)[2]), "+f"((d)[3]) \
        : "r"((a)[0]), "r"((a)[1]), "r"((a)[2]), "r"((a)[3]), "r"(b0), "r"(b1))

// ---- convert kernels ----
__device__ __forceinline__ void split8(const float* src, uint32_t* hp, uint32_t* lp) {
    float4 v0 = *(const float4*)(src);
    float4 v1 = *(const float4*)(src + 4);
    float v[8] = {v0.x, v0.y, v0.z, v0.w, v1.x, v1.y, v1.z, v1.w};
#pragma unroll
    for (int i = 0; i < 4; ++i) {
        __nv_bfloat16 h0 = __float2bfloat16(v[2 * i]);
        __nv_bfloat16 h1 = __float2bfloat16(v[2 * i + 1]);
        __nv_bfloat16 l0 = __float2bfloat16(v[2 * i] - __bfloat162float(h0));
        __nv_bfloat16 l1 = __float2bfloat16(v[2 * i + 1] - __bfloat162float(h1));
        hp[i] = (uint32_t)__bfloat16_as_ushort(h0) | ((uint32_t)__bfloat16_as_ushort(h1) << 16);
        lp[i] = (uint32_t)__bfloat16_as_ushort(l0) | ((uint32_t)__bfloat16_as_ushort(l1) << 16);
    }
}

__global__ void cvt_x_kernel(const float* __restrict__ x) {
    size_t idx = (size_t)blockIdx.x * 256 + threadIdx.x;  // M*K/8 threads
    size_t off8 = idx << 3;
    uint32_t hp[4], lp[4];
    split8(x + off8, hp, lp);
    *(uint4*)(g_xhi + off8 * 2) = make_uint4(hp[0], hp[1], hp[2], hp[3]);
    *(uint4*)(g_xlo + off8 * 2) = make_uint4(lp[0], lp[1], lp[2], lp[3]);
}

__global__ void cvt_w_kernel(const float* __restrict__ W) {
    size_t idx = (size_t)blockIdx.x * 256 + threadIdx.x;  // N*K/8 threads
    size_t off8 = idx << 3;
    uint32_t hp[4], lp[4];
    split8(W + off8, hp, lp);
    *(uint4*)(g_whi + off8 * 2) = make_uint4(hp[0], hp[1], hp[2], hp[3]);
    *(uint4*)(g_wlo + off8 * 2) = make_uint4(lp[0], lp[1], lp[2], lp[3]);
}

__global__ void cvt_alpha_kernel(const float* __restrict__ decay) {
    int i = blockIdx.x * 256 + threadIdx.x;
    if (i < N_DIM) g_alpha[i] = 1.0f / (1.0f + expf(-decay[i]));
}

// ---- GEMM ----
// SMEM stage layout: A tile rows 0..127, each row 128B = [hi 64B | lo 64B], SW128-XOR swizzled.
//                    B tile same, at +16384.
__device__ __forceinline__ void issue_stage_loads(uint32_t sb, int stg, int kt,
                                                  int mBase, int nBase, int tid) {
    const uint32_t sA = sb + stg * STAGE_BYTES;
    const uint32_t sB = sA + 16384;
    const int row = tid >> 1;
    const int half = tid & 1;
    const uint32_t rx = (uint32_t)((row & 7) << 4);

    const unsigned char* srcA = (half ? g_xlo : g_xhi) +
        (((size_t)(mBase + row) * K_DIM + (size_t)kt * BK) << 1);
    const unsigned char* srcB = (half ? g_wlo : g_whi) +
        (((size_t)(nBase + row) * K_DIM + (size_t)kt * BK) << 1);
#pragma unroll
    for (int c = 0; c < 4; ++c) {
        const uint32_t doff = (uint32_t)row * 128 + (((uint32_t)(half * 64 + c * 16)) ^ rx);
        CP16(sA + doff, srcA + c * 16);
        CP16(sB + doff, srcB + c * 16);
    }
}

__global__ void __launch_bounds__(NTHREADS, 1)
lrnn_gemm_hmma(const float* __restrict__ h,
               const float* __restrict__ bias,
               float* __restrict__ out,
               int write_twice)
{
    extern __shared__ char smem[];
    const uint32_t sb = smem_u32(smem);
    const int tid  = threadIdx.x;
    const int lane = tid & 31;
    const int wid  = tid >> 5;
    const int wm = wid >> 2;          // 0..1  (64-row strip)
    const int wn = wid & 3;           // 0..3  (32-col strip)
    const int nBase = blockIdx.x * BN;
    const int mBase = blockIdx.y * BM;

    float d[4][4][4];
#pragma unroll
    for (int i = 0; i < 4; ++i)
#pragma unroll
        for (int j = 0; j < 4; ++j)
#pragma unroll
            for (int q = 0; q < 4; ++q) d[i][j][q] = 0.0f;

    // prologue: stages 0 and 1
    issue_stage_loads(sb, 0, 0, mBase, nBase, tid);
    CP_COMMIT();
    issue_stage_loads(sb, 1, 1, mBase, nBase, tid);
    CP_COMMIT();

    // per-lane ldmatrix addressing constants
    const uint32_t rx  = (uint32_t)((lane & 7) << 4);   // swizzle XOR
    const uint32_t kl  = (uint32_t)(lane & 16);         // k8 half select
    const uint32_t rowA = (uint32_t)(wm * 64 + (lane & 15)) * 128;
    const uint32_t rowB = (uint32_t)(wn * 32 + (lane & 15)) * 128 + 16384;

    for (int t = 0; t < KTILES; ++t) {
        CP_WAIT1();
        __syncthreads();

        // issue loads for t+2 (buffer (t+2)%3 was last read in iter t-1 -> safe after sync)
        if (t + 2 < KTILES)
            issue_stage_loads(sb, (t + 2) % STAGES, t + 2, mBase, nBase, tid);
        CP_COMMIT();

        const uint32_t sg = sb + (uint32_t)(t % STAGES) * STAGE_BYTES;

#pragma unroll
        for (int ks = 0; ks < 2; ++ks) {
            const uint32_t bHiOff = (((uint32_t)(ks * 32)) + kl) ^ rx;
            const uint32_t bLoOff = (((uint32_t)(ks * 32 + 64)) + kl) ^ rx;

            uint32_t aH[4][4], aL[4][4];
#pragma unroll
            for (int i = 0; i < 4; ++i) {
                const uint32_t ra = sg + rowA + (uint32_t)(i * 16) * 128;
                LDSM_X4(aH[i][0], aH[i][1], aH[i][2], aH[i][3], ra + bHiOff);
                LDSM_X4(aL[i][0], aL[i][1], aL[i][2], aL[i][3], ra + bLoOff);
            }
            uint32_t bH[4][2], bL[4][2];
#pragma unroll
            for (int jp = 0; jp < 2; ++jp) {
                const uint32_t rb = sg + rowB + (uint32_t)(jp * 16) * 128;
                uint32_t r0, r1, r2, r3;
                LDSM_X4(r0, r1, r2, r3, rb + bHiOff);
                bH[jp * 2][0] = r0; bH[jp * 2 + 1][0] = r1;
                bH[jp * 2][1] = r2; bH[jp * 2 + 1][1] = r3;
                LDSM_X4(r0, r1, r2, r3, rb + bLoOff);
                bL[jp * 2][0] = r0; bL[jp * 2 + 1][0] = r1;
                bL[jp * 2][1] = r2; bL[jp * 2 + 1][1] = r3;
            }
#pragma unroll
            for (int i = 0; i < 4; ++i)
#pragma unroll
                for (int j = 0; j < 4; ++j) {
                    MMA_BF16(d[i][j], aH[i], bH[j][0], bH[j][1]);  // hi*hi
                    MMA_BF16(d[i][j], aH[i], bL[j][0], bL[j][1]);  // hi*lo
                    MMA_BF16(d[i][j], aL[i], bH[j][0], bH[j][1]);  // lo*hi
                }
        }
    }

    // ---- fused epilogue ----
    const size_t dual = (size_t)M_DIM * N_DIM;
#pragma unroll
    for (int j = 0; j < 4; ++j) {
        const int c = nBase + wn * 32 + j * 8 + (lane & 3) * 2;
        const float al0 = g_alpha[c],  al1 = g_alpha[c + 1];
        const float bb0 = bias[c],     bb1 = bias[c + 1];
#pragma unroll
        for (int i = 0; i < 4; ++i) {
            const int r0 = mBase + wm * 64 + i * 16 + (lane >> 2);
            const size_t o0 = (size_t)r0 * N_DIM + c;
            const size_t o1 = o0 + 8 * N_DIM;
            float2 h0 = *(const float2*)(h + o0);
            float2 h1 = *(const float2*)(h + o1);
            float2 v0, v1;
            v0.x = fmaf(al0, h0.x, d[i][j][0] + bb0);
            v0.y = fmaf(al1, h0.y, d[i][j][1] + bb1);
            v1.x = fmaf(al0, h1.x, d[i][j][2] + bb0);
            v1.y = fmaf(al1, h1.y, d[i][j][3] + bb1);
            *(float2*)(out + o0) = v0;
            *(float2*)(out + o1) = v1;
            if (write_twice) {
                *(float2*)(out + dual + o0) = v0;
                *(float2*)(out + dual + o1) = v1;
            }
        }
    }
}

extern "C" void kernel_launch(void* const* d_in, const int* in_sizes, int n_in,
                              void* d_out, int out_size)
{
    const float* x     = (const float*)d_in[0];
    const float* h     = (const float*)d_in[1];
    const float* W     = (const float*)d_in[2];
    const float* b     = (const float*)d_in[3];
    const float* decay = (const float*)d_in[4];
    float* out = (float*)d_out;

    const long long total = (long long)M_DIM * N_DIM;
    const int write_twice = ((long long)out_size >= 2 * total) ? 1 : 0;

    cudaFuncSetAttribute(lrnn_gemm_hmma, cudaFuncAttributeMaxDynamicSharedMemorySize, SMEM_TOTAL);

    cvt_x_kernel<<<(int)(((size_t)M_DIM * K_DIM / 8) / 256), 256>>>(x);
    cvt_w_kernel<<<(int)(((size_t)N_DIM * K_DIM / 8) / 256), 256>>>(W);
    cvt_alpha_kernel<<<(N_DIM + 255) / 256, 256>>>(decay);

    dim3 grid(N_DIM / BN, M_DIM / BM);   // (16, 128)
    lrnn_gemm_hmma<<<grid, NTHREADS, SMEM_TOTAL>>>(h, b, out, write_twice);
}